// round 1
// baseline (speedup 1.0000x reference)
#include <cuda_runtime.h>
#include <math.h>

#define NSENT 4096
#define NWORD 65536
#define NSEC  512
#define NHEAD 8
#define CDIM  640
#define HC    5120
#define EW    65536
#define ES    32768
#define ESEC  4096
#define NEG_SLOPE 0.2f

// ---------------- scratch (__device__ globals, no allocation) ----------------
__device__ float g_Uw[NSENT*HC];
__device__ float g_Us[NSENT*HC];
__device__ float g_USec[NSENT*HC];
__device__ float g_U1[NSENT*HC];
__device__ float g_U2[NSENT*HC];
__device__ float g_Gw[NSENT*NHEAD*300];
__device__ float g_Gs[NSENT*NHEAD*640];
__device__ float g_GS[NSENT*NHEAD*512];
__device__ float g_Hh[NSENT*640];
__device__ float g_Pws[300*8], g_Pwd[640*8], g_Pss[640*8], g_Psd[640*8], g_PSs[512*8], g_PSd[640*8];
__device__ float g_alws[NWORD*8];
__device__ float g_alwd[NSENT*8], g_alss[NSENT*8], g_alsd[NSENT*8], g_alSd[NSENT*8];
__device__ float g_alSs[NSEC*8];
__device__ float g_aw[EW*8], g_as[ES*8], g_aS[ESEC*8];   // logits -> ex -> alpha, in place
__device__ int   g_mw[NSENT*8], g_ms[NSENT*8], g_mS[NSENT*8];
__device__ float g_dw[NSENT*8], g_ds[NSENT*8], g_dS[NSENT*8];
__device__ int   g_cw[NSENT], g_cs[NSENT], g_cS[NSENT];
__device__ int   g_ow[NSENT+1], g_os[NSENT+1], g_oS[NSENT+1];
__device__ int   g_uw[NSENT], g_us[NSENT], g_uS[NSENT];
__device__ int   g_ew[EW], g_es[ES], g_eS[ESEC];

// ---------------- helpers ----------------
__device__ __forceinline__ int f2oi(float f){ int i=__float_as_int(f); return i>=0? i : (i ^ 0x7fffffff); }
__device__ __forceinline__ float oi2f(int i){ return __int_as_float(i>=0? i : (i ^ 0x7fffffff)); }

// ---------------- init ----------------
__global__ void k_init_gat(int* segmax, float* den, int* cnt, int n){
    int i = blockIdx.x*blockDim.x + threadIdx.x;
    if (i < n){ segmax[i] = (int)0x807FFFFF; den[i] = 0.f; }   // f2oi(-inf)
    if (i < n/8) cnt[i] = 0;
}

// P[d,h] = sum_c W[d, h*640+c] * a[h,c]   (one warp per (d,h))
__global__ void k_P(const float* __restrict__ W, const float* __restrict__ a,
                    float* __restrict__ P, int D){
    int gw   = (blockIdx.x*blockDim.x + threadIdx.x) >> 5;
    int lane = threadIdx.x & 31;
    if (gw >= D*8) return;
    int d = gw >> 3, h = gw & 7;
    const float* wr = W + (long)d*HC + h*CDIM;
    const float* ar = a + h*CDIM;
    float acc = 0.f;
    for (int c = lane; c < CDIM; c += 32) acc = fmaf(wr[c], ar[c], acc);
    #pragma unroll
    for (int o = 16; o; o >>= 1) acc += __shfl_xor_sync(0xffffffffu, acc, o);
    if (!lane) P[gw] = acc;
}

// AL[n,h] = sum_d X[n,d]*P[d,h]   (one warp per row)
__global__ void k_xp(const float* __restrict__ X, const float* __restrict__ P,
                     float* __restrict__ AL, int N, int D){
    int row  = (blockIdx.x*blockDim.x + threadIdx.x) >> 5;
    int lane = threadIdx.x & 31;
    if (row >= N) return;
    const float* x = X + (long)row*D;
    float acc[8] = {0,0,0,0,0,0,0,0};
    for (int dd = lane; dd < D; dd += 32){
        float xv = x[dd];
        const float* p = P + dd*8;
        #pragma unroll
        for (int h = 0; h < 8; h++) acc[h] = fmaf(xv, p[h], acc[h]);
    }
    #pragma unroll
    for (int h = 0; h < 8; h++){
        #pragma unroll
        for (int o = 16; o; o >>= 1) acc[h] += __shfl_xor_sync(0xffffffffu, acc[h], o);
    }
    if (lane == 0){
        #pragma unroll
        for (int h = 0; h < 8; h++) AL[(long)row*8 + h] = acc[h];
    }
}

// ---------------- edge softmax ----------------
__global__ void k_logits(const int* __restrict__ src, const int* __restrict__ dst,
                         const float* __restrict__ als, const float* __restrict__ ald,
                         float* __restrict__ lg, int* __restrict__ segmax, int E){
    int e = blockIdx.x*blockDim.x + threadIdx.x;
    if (e >= E) return;
    int s = src[e], d = dst[e];
    #pragma unroll
    for (int h = 0; h < 8; h++){
        float v = als[s*8+h] + ald[d*8+h];
        v = v > 0.f ? v : NEG_SLOPE*v;
        lg[e*8+h] = v;
        atomicMax(&segmax[d*8+h], f2oi(v));
    }
}

__global__ void k_exp(const int* __restrict__ dst, float* __restrict__ lg,
                      const int* __restrict__ segmax, float* __restrict__ den, int E){
    int e = blockIdx.x*blockDim.x + threadIdx.x;
    if (e >= E) return;
    int d = dst[e];
    #pragma unroll
    for (int h = 0; h < 8; h++){
        float m  = oi2f(segmax[d*8+h]);
        float ex = expf(lg[e*8+h] - m);
        lg[e*8+h] = ex;
        atomicAdd(&den[d*8+h], ex);
    }
}

__global__ void k_alpha(const int* __restrict__ dst, float* __restrict__ lg,
                        const float* __restrict__ den, int E){
    int e = blockIdx.x*blockDim.x + threadIdx.x;
    if (e >= E) return;
    int d = dst[e];
    #pragma unroll
    for (int h = 0; h < 8; h++)
        lg[e*8+h] = lg[e*8+h] / (den[d*8+h] + 1e-16f);
}

// ---------------- CSR build ----------------
__global__ void k_count(const int* __restrict__ dst, int* __restrict__ cnt, int E){
    int e = blockIdx.x*blockDim.x + threadIdx.x;
    if (e < E) atomicAdd(&cnt[dst[e]], 1);
}

__global__ void k_scan(const int* __restrict__ cnt, int* __restrict__ offs,
                       int* __restrict__ cur){   // 1 block, 1024 threads, n = 4096
    __shared__ int sh[1024];
    int tid = threadIdx.x;
    int base = tid*4;
    int v0 = cnt[base], v1 = cnt[base+1], v2 = cnt[base+2], v3 = cnt[base+3];
    int sum = v0+v1+v2+v3;
    sh[tid] = sum; __syncthreads();
    for (int off = 1; off < 1024; off <<= 1){
        int t = (tid >= off) ? sh[tid-off] : 0;
        __syncthreads();
        sh[tid] += t;
        __syncthreads();
    }
    int run = sh[tid] - sum;
    offs[base] = run;   cur[base]   = run; run += v0;
    offs[base+1] = run; cur[base+1] = run; run += v1;
    offs[base+2] = run; cur[base+2] = run; run += v2;
    offs[base+3] = run; cur[base+3] = run; run += v3;
    if (tid == 1023) offs[NSENT] = run;
}

__global__ void k_scatter(const int* __restrict__ dst, int* __restrict__ cur,
                          int* __restrict__ eidx, int E){
    int e = blockIdx.x*blockDim.x + threadIdx.x;
    if (e < E) eidx[atomicAdd(&cur[dst[e]], 1)] = e;
}

// ---------------- per-dst aggregation (raw features, weighted by alpha) ----------------
// G[d,h,c] = sum_{e in dst d} alpha[e,h] * X[src_e, c]
template<int D, int COLS>
__global__ void k_agg(const float* __restrict__ X, const int* __restrict__ src,
                      const int* __restrict__ eidx, const int* __restrict__ offs,
                      const float* __restrict__ alpha, float* __restrict__ G){
    int d = blockIdx.x, tid = threadIdx.x;
    float acc[COLS][8];
    #pragma unroll
    for (int ci = 0; ci < COLS; ci++)
        #pragma unroll
        for (int h = 0; h < 8; h++) acc[ci][h] = 0.f;
    int beg = offs[d], end = offs[d+1];
    for (int i = beg; i < end; i++){
        int e = eidx[i];
        int s = src[e];
        float a[8];
        #pragma unroll
        for (int h = 0; h < 8; h++) a[h] = __ldg(&alpha[e*8+h]);
        #pragma unroll
        for (int ci = 0; ci < COLS; ci++){
            int c = tid + ci*256;
            if (c < D){
                float x = __ldg(&X[(long)s*D + c]);
                #pragma unroll
                for (int h = 0; h < 8; h++) acc[ci][h] = fmaf(a[h], x, acc[ci][h]);
            }
        }
    }
    #pragma unroll
    for (int ci = 0; ci < COLS; ci++){
        int c = tid + ci*256;
        if (c < D){
            #pragma unroll
            for (int h = 0; h < 8; h++)
                G[((long)d*8 + h)*D + c] = acc[ci][h];
        }
    }
}

// ---------------- SGEMM 128x128x16, 8x8 microtile, fused epilogues ----------------
#define BM 128
#define BN 128
#define BK 16
enum { EPI_BIAS_ELU = 0, EPI_BIAS_RELU, EPI_FUSION, EPI_RESID };

template<int EPI>
__global__ __launch_bounds__(256,2)
void gemm_k(const float* __restrict__ A, const float* __restrict__ A2, int ksplit,
            const float* __restrict__ B, float* __restrict__ C,
            const float* __restrict__ bias,
            const float* __restrict__ E0, const float* __restrict__ E1,
            int M, int N, int K, int lda, int ldb, int ldc,
            long sA, long sB, long sC, int sBias){
    int z = blockIdx.z;
    A  += (long)z*sA;  A2 += (long)z*sA;
    B  += (long)z*sB;  C  += (long)z*sC;
    const float* bp = bias + (long)z*sBias;

    __shared__ float As[BK][BM];
    __shared__ float Bs[BK][BN];
    int tid = threadIdx.x;
    int bRow = blockIdx.y*BM, bCol = blockIdx.x*BN;
    int aRow = tid >> 2, aCol = (tid & 3) << 2;
    int bR   = tid >> 5, bC   = (tid & 31) << 2;
    int tr = (tid >> 4) << 3, tc = (tid & 15) << 3;

    float acc[8][8];
    #pragma unroll
    for (int i = 0; i < 8; i++)
        #pragma unroll
        for (int j = 0; j < 8; j++) acc[i][j] = 0.f;

    for (int k0 = 0; k0 < K; k0 += BK){
        #pragma unroll
        for (int r = 0; r < 2; r++){
            int row = aRow + r*64;
            int gk  = k0 + aCol;
            float4 v = make_float4(0.f,0.f,0.f,0.f);
            if (gk < K){
                const float* srcp = (gk < ksplit)
                    ? (A  + (long)(bRow+row)*lda + gk)
                    : (A2 + (long)(bRow+row)*lda + (gk - ksplit));
                v = *reinterpret_cast<const float4*>(srcp);
            }
            As[aCol+0][row] = v.x; As[aCol+1][row] = v.y;
            As[aCol+2][row] = v.z; As[aCol+3][row] = v.w;
        }
        #pragma unroll
        for (int r = 0; r < 2; r++){
            int row = bR + r*8;
            int gk  = k0 + row;
            float4 v = make_float4(0.f,0.f,0.f,0.f);
            if (gk < K) v = *reinterpret_cast<const float4*>(B + (long)gk*ldb + bCol + bC);
            *reinterpret_cast<float4*>(&Bs[row][bC]) = v;
        }
        __syncthreads();
        #pragma unroll
        for (int kk = 0; kk < BK; kk++){
            float4 ra0 = *reinterpret_cast<const float4*>(&As[kk][tr]);
            float4 ra1 = *reinterpret_cast<const float4*>(&As[kk][tr+4]);
            float4 rb0 = *reinterpret_cast<const float4*>(&Bs[kk][tc]);
            float4 rb1 = *reinterpret_cast<const float4*>(&Bs[kk][tc+4]);
            float ra[8] = {ra0.x,ra0.y,ra0.z,ra0.w,ra1.x,ra1.y,ra1.z,ra1.w};
            float rb[8] = {rb0.x,rb0.y,rb0.z,rb0.w,rb1.x,rb1.y,rb1.z,rb1.w};
            #pragma unroll
            for (int i = 0; i < 8; i++)
                #pragma unroll
                for (int j = 0; j < 8; j++)
                    acc[i][j] = fmaf(ra[i], rb[j], acc[i][j]);
        }
        __syncthreads();
    }

    #pragma unroll
    for (int i = 0; i < 8; i++){
        int row = bRow + tr + i;
        #pragma unroll
        for (int j = 0; j < 8; j++){
            int col = bCol + tc + j;
            long idx = (long)row*ldc + col;
            float v = acc[i][j] + bp[col];
            if (EPI == EPI_BIAS_ELU){
                C[idx] = v > 0.f ? v : (expf(v) - 1.f);
            } else if (EPI == EPI_BIAS_RELU){
                C[idx] = fmaxf(v, 0.f);
            } else if (EPI == EPI_FUSION){
                float zg = 1.f/(1.f + expf(-v));
                C[idx] = zg*E0[idx] + (1.f - zg)*E1[idx];
            } else { // EPI_RESID
                C[idx] = E0[idx] + v;
            }
        }
    }
}

// ---------------- host ----------------
#define SYMF(name, sym) float* name; cudaGetSymbolAddress((void**)&name, sym)
#define SYMI(name, sym) int*   name; cudaGetSymbolAddress((void**)&name, sym)

extern "C" void kernel_launch(void* const* d_in, const int* in_sizes, int n_in,
                              void* d_out, int out_size){
    const float* Hs    = (const float*)d_in[0];
    const float* Hw    = (const float*)d_in[1];
    const float* HSc   = (const float*)d_in[2];
    const int*   w2s   = (const int*)d_in[3];
    const int*   s2s   = (const int*)d_in[4];
    const int*   S2s   = (const int*)d_in[5];
    const float* Ww_src= (const float*)d_in[6];
    const float* Ww_dst= (const float*)d_in[7];
    const float* aw_src= (const float*)d_in[8];
    const float* aw_dst= (const float*)d_in[9];
    const float* bw    = (const float*)d_in[10];
    const float* Ws    = (const float*)d_in[11];
    const float* as_src= (const float*)d_in[12];
    const float* as_dst= (const float*)d_in[13];
    const float* bs    = (const float*)d_in[14];
    const float* WS_src= (const float*)d_in[15];
    const float* WS_dst= (const float*)d_in[16];
    const float* aS_src= (const float*)d_in[17];
    const float* aS_dst= (const float*)d_in[18];
    const float* bS    = (const float*)d_in[19];
    const float* Wf1   = (const float*)d_in[20];
    const float* bf1   = (const float*)d_in[21];
    const float* Wf2   = (const float*)d_in[22];
    const float* bf2   = (const float*)d_in[23];
    const float* W1    = (const float*)d_in[24];
    const float* b1    = (const float*)d_in[25];
    const float* W2    = (const float*)d_in[26];
    const float* b2    = (const float*)d_in[27];
    float* out = (float*)d_out;

    SYMF(Uw, g_Uw); SYMF(Us, g_Us); SYMF(USec, g_USec); SYMF(U1, g_U1); SYMF(U2, g_U2);
    SYMF(Gw, g_Gw); SYMF(Gs, g_Gs); SYMF(GS, g_GS); SYMF(Hh, g_Hh);
    SYMF(Pws, g_Pws); SYMF(Pwd, g_Pwd); SYMF(Pss, g_Pss); SYMF(Psd, g_Psd);
    SYMF(PSs, g_PSs); SYMF(PSd, g_PSd);
    SYMF(alws, g_alws); SYMF(alwd, g_alwd); SYMF(alss, g_alss); SYMF(alsd, g_alsd);
    SYMF(alSs, g_alSs); SYMF(alSd, g_alSd);
    SYMF(aw, g_aw); SYMF(as, g_as); SYMF(aS, g_aS);
    SYMI(mw, g_mw); SYMI(ms, g_ms); SYMI(mS, g_mS);
    SYMF(dw, g_dw); SYMF(ds, g_ds); SYMF(dS, g_dS);
    SYMI(cw, g_cw); SYMI(cs, g_cs); SYMI(cS, g_cS);
    SYMI(ow, g_ow); SYMI(os_, g_os); SYMI(oS, g_oS);
    SYMI(uw, g_uw); SYMI(us, g_us); SYMI(uS, g_uS);
    SYMI(ew, g_ew); SYMI(es, g_es); SYMI(eS, g_eS);

    const int* src_w = w2s;            const int* dst_w = w2s + EW;
    const int* src_s = s2s;            const int* dst_s = s2s + ES;
    const int* src_S = S2s;            const int* dst_S = S2s + ESEC;

    // init
    k_init_gat<<<(NSENT*8+255)/256, 256>>>(mw, dw, cw, NSENT*8);
    k_init_gat<<<(NSENT*8+255)/256, 256>>>(ms, ds, cs, NSENT*8);
    k_init_gat<<<(NSENT*8+255)/256, 256>>>(mS, dS, cS, NSENT*8);

    // per-head attention projection vectors
    k_P<<<300, 256>>>(Ww_src, aw_src, Pws, 300);
    k_P<<<640, 256>>>(Ww_dst, aw_dst, Pwd, 640);
    k_P<<<640, 256>>>(Ws,     as_src, Pss, 640);
    k_P<<<640, 256>>>(Ws,     as_dst, Psd, 640);
    k_P<<<512, 256>>>(WS_src, aS_src, PSs, 512);
    k_P<<<640, 256>>>(WS_dst, aS_dst, PSd, 640);

    // attention logits per node
    k_xp<<<NWORD/8, 256>>>(Hw,  Pws, alws, NWORD, 300);
    k_xp<<<NSENT/8, 256>>>(Hs,  Pwd, alwd, NSENT, 640);
    k_xp<<<NSENT/8, 256>>>(Hs,  Pss, alss, NSENT, 640);
    k_xp<<<NSENT/8, 256>>>(Hs,  Psd, alsd, NSENT, 640);
    k_xp<<<NSEC/8,  256>>>(HSc, PSs, alSs, NSEC,  512);
    k_xp<<<NSENT/8, 256>>>(Hs,  PSd, alSd, NSENT, 640);

    // CSR build
    k_count<<<EW/256, 256>>>(dst_w, cw, EW);
    k_count<<<ES/256, 256>>>(dst_s, cs, ES);
    k_count<<<ESEC/256, 256>>>(dst_S, cS, ESEC);
    k_scan<<<1, 1024>>>(cw, ow, uw);
    k_scan<<<1, 1024>>>(cs, os_, us);
    k_scan<<<1, 1024>>>(cS, oS, uS);
    k_scatter<<<EW/256, 256>>>(dst_w, uw, ew, EW);
    k_scatter<<<ES/256, 256>>>(dst_s, us, es, ES);
    k_scatter<<<ESEC/256, 256>>>(dst_S, uS, eS, ESEC);

    // edge softmax
    k_logits<<<EW/256, 256>>>(src_w, dst_w, alws, alwd, aw, mw, EW);
    k_logits<<<ES/256, 256>>>(src_s, dst_s, alss, alsd, as, ms, ES);
    k_logits<<<ESEC/256, 256>>>(src_S, dst_S, alSs, alSd, aS, mS, ESEC);
    k_exp<<<EW/256, 256>>>(dst_w, aw, mw, dw, EW);
    k_exp<<<ES/256, 256>>>(dst_s, as, ms, ds, ES);
    k_exp<<<ESEC/256, 256>>>(dst_S, aS, mS, dS, ESEC);
    k_alpha<<<EW/256, 256>>>(dst_w, aw, dw, EW);
    k_alpha<<<ES/256, 256>>>(dst_s, as, ds, ES);
    k_alpha<<<ESEC/256, 256>>>(dst_S, aS, dS, ESEC);

    // aggregate raw features per (dst, head)
    k_agg<300,2><<<NSENT, 256>>>(Hw,  src_w, ew, ow,  aw, Gw);
    k_agg<640,3><<<NSENT, 256>>>(Hs,  src_s, es, os_, as, Gs);
    k_agg<512,2><<<NSENT, 256>>>(HSc, src_S, eS, oS,  aS, GS);

    // per-head projection + bias + ELU   (batched over heads via blockIdx.z)
    dim3 gp(CDIM/BN, NSENT/BM, 8);
    gemm_k<EPI_BIAS_ELU><<<gp, 256>>>(Gw, Gw, 300, Ww_src, Uw,  bw, nullptr, nullptr,
                                      NSENT, CDIM, 300, 8*300, HC, HC, 300, 640, 640, 640);
    gemm_k<EPI_BIAS_ELU><<<gp, 256>>>(Gs, Gs, 640, Ws,     Us,  bs, nullptr, nullptr,
                                      NSENT, CDIM, 640, 8*640, HC, HC, 640, 640, 640, 640);
    gemm_k<EPI_BIAS_ELU><<<gp, 256>>>(GS, GS, 512, WS_src, USec, bS, nullptr, nullptr,
                                      NSENT, CDIM, 512, 8*512, HC, HC, 512, 640, 640, 640);

    // fusion gates: single GEMM with implicit concat (A-split), fused sigmoid-gate epilogue
    dim3 gf(HC/BN, NSENT/BM, 1);
    gemm_k<EPI_FUSION><<<gf, 256>>>(Uw, Us, HC, Wf1, U1, bf1, Uw, Us,
                                    NSENT, HC, 2*HC, HC, HC, HC, 0, 0, 0, 0);
    gemm_k<EPI_FUSION><<<gf, 256>>>(U1, USec, HC, Wf2, U2, bf2, U1, USec,
                                    NSENT, HC, 2*HC, HC, HC, HC, 0, 0, 0, 0);

    // FFN + residual
    dim3 g1(CDIM/BN, NSENT/BM, 1);
    gemm_k<EPI_BIAS_RELU><<<g1, 256>>>(U2, U2, HC, W1, Hh, b1, nullptr, nullptr,
                                       NSENT, CDIM, HC, HC, CDIM, CDIM, 0, 0, 0, 0);
    gemm_k<EPI_RESID><<<g1, 256>>>(Hh, Hh, CDIM, W2, out, b2, Hs, nullptr,
                                   NSENT, CDIM, CDIM, CDIM, CDIM, CDIM, 0, 0, 0, 0);
}

// round 3
// speedup vs baseline: 1.0004x; 1.0004x over previous
#include <cuda_runtime.h>
#include <math.h>

#define NSENT 4096
#define NWORD 65536
#define NSEC  512
#define NHEAD 8
#define CDIM  640
#define HC    5120
#define EW    65536
#define ES    32768
#define ESEC  4096
#define NEG_SLOPE 0.2f

// ---------------- scratch (__device__ globals, no allocation) ----------------
__device__ float g_Uw[NSENT*HC];
__device__ float g_Us[NSENT*HC];
__device__ float g_USec[NSENT*HC];
__device__ float g_U1[NSENT*HC];
__device__ float g_U2[NSENT*HC];
__device__ float g_Gw[NSENT*NHEAD*300];
__device__ float g_Gs[NSENT*NHEAD*640];
__device__ float g_GS[NSENT*NHEAD*512];
__device__ float g_Hh[NSENT*640];
__device__ float g_Pws[300*8], g_Pwd[640*8], g_Pss[640*8], g_Psd[640*8], g_PSs[512*8], g_PSd[640*8];
__device__ float g_alws[NWORD*8];
__device__ float g_alwd[NSENT*8], g_alss[NSENT*8], g_alsd[NSENT*8], g_alSd[NSENT*8];
__device__ float g_alSs[NSEC*8];
__device__ float g_aw[EW*8], g_as[ES*8], g_aS[ESEC*8];   // logits -> ex -> alpha, in place
__device__ int   g_mw[NSENT*8], g_ms[NSENT*8], g_mS[NSENT*8];
__device__ float g_dw[NSENT*8], g_ds[NSENT*8], g_dS[NSENT*8];
__device__ int   g_cw[NSENT], g_cs[NSENT], g_cS[NSENT];
__device__ int   g_ow[NSENT+1], g_os[NSENT+1], g_oS[NSENT+1];
__device__ int   g_uw[NSENT], g_us[NSENT], g_uS[NSENT];
__device__ int   g_ew[EW], g_es[ES], g_eS[ESEC];

// ---------------- helpers ----------------
__device__ __forceinline__ int f2oi(float f){ int i=__float_as_int(f); return i>=0? i : (i ^ 0x7fffffff); }
__device__ __forceinline__ float oi2f(int i){ return __int_as_float(i>=0? i : (i ^ 0x7fffffff)); }

// ---------------- init (all three graphs in one launch) ----------------
__global__ void k_init_all(int* m0, float* d0, int* c0,
                           int* m1, float* d1, int* c1,
                           int* m2, float* d2, int* c2){
    int i = blockIdx.x*blockDim.x + threadIdx.x;
    if (i < NSENT*8){
        m0[i] = (int)0x807FFFFF; d0[i] = 0.f;
        m1[i] = (int)0x807FFFFF; d1[i] = 0.f;
        m2[i] = (int)0x807FFFFF; d2[i] = 0.f;
    }
    if (i < NSENT){ c0[i] = 0; c1[i] = 0; c2[i] = 0; }
}

// P[d,h] = sum_c W[d, h*640+c] * a[h,c]   (one warp per (d,h))
__global__ void k_P(const float* __restrict__ W, const float* __restrict__ a,
                    float* __restrict__ P, int D){
    int gw   = (blockIdx.x*blockDim.x + threadIdx.x) >> 5;
    int lane = threadIdx.x & 31;
    if (gw >= D*8) return;
    int d = gw >> 3, h = gw & 7;
    const float* wr = W + (long)d*HC + h*CDIM;
    const float* ar = a + h*CDIM;
    float acc = 0.f;
    for (int c = lane; c < CDIM; c += 32) acc = fmaf(__ldg(&wr[c]), __ldg(&ar[c]), acc);
    #pragma unroll
    for (int o = 16; o; o >>= 1) acc += __shfl_xor_sync(0xffffffffu, acc, o);
    if (!lane) P[gw] = acc;
}

// AL[n,h] = sum_d X[n,d]*P[d,h]   (one warp per row)
__global__ void k_xp(const float* __restrict__ X, const float* __restrict__ P,
                     float* __restrict__ AL, int N, int D){
    int row  = (blockIdx.x*blockDim.x + threadIdx.x) >> 5;
    int lane = threadIdx.x & 31;
    if (row >= N) return;
    const float* x = X + (long)row*D;
    float acc[8] = {0,0,0,0,0,0,0,0};
    for (int dd = lane; dd < D; dd += 32){
        float xv = __ldg(&x[dd]);
        const float* p = P + dd*8;
        #pragma unroll
        for (int h = 0; h < 8; h++) acc[h] = fmaf(xv, __ldg(&p[h]), acc[h]);
    }
    #pragma unroll
    for (int h = 0; h < 8; h++){
        #pragma unroll
        for (int o = 16; o; o >>= 1) acc[h] += __shfl_xor_sync(0xffffffffu, acc[h], o);
    }
    if (lane == 0){
        #pragma unroll
        for (int h = 0; h < 8; h++) AL[(long)row*8 + h] = acc[h];
    }
}

// ---------------- edge softmax ----------------
__global__ void k_logits(const int* __restrict__ src, const int* __restrict__ dst,
                         const float* __restrict__ als, const float* __restrict__ ald,
                         float* __restrict__ lg, int* __restrict__ segmax, int E){
    int e = blockIdx.x*blockDim.x + threadIdx.x;
    if (e >= E) return;
    int s = src[e], d = dst[e];
    #pragma unroll
    for (int h = 0; h < 8; h++){
        float v = __ldg(&als[s*8+h]) + __ldg(&ald[d*8+h]);
        v = v > 0.f ? v : NEG_SLOPE*v;
        lg[e*8+h] = v;
        atomicMax(&segmax[d*8+h], f2oi(v));
    }
}

__global__ void k_exp(const int* __restrict__ dst, float* __restrict__ lg,
                      const int* __restrict__ segmax, float* __restrict__ den, int E){
    int e = blockIdx.x*blockDim.x + threadIdx.x;
    if (e >= E) return;
    int d = dst[e];
    #pragma unroll
    for (int h = 0; h < 8; h++){
        float m  = oi2f(__ldg(&segmax[d*8+h]));
        float ex = expf(lg[e*8+h] - m);
        lg[e*8+h] = ex;
        atomicAdd(&den[d*8+h], ex);
    }
}

__global__ void k_alpha(const int* __restrict__ dst, float* __restrict__ lg,
                        const float* __restrict__ den, int E){
    int e = blockIdx.x*blockDim.x + threadIdx.x;
    if (e >= E) return;
    int d = dst[e];
    #pragma unroll
    for (int h = 0; h < 8; h++)
        lg[e*8+h] = lg[e*8+h] / (__ldg(&den[d*8+h]) + 1e-16f);
}

// ---------------- CSR build ----------------
__global__ void k_count(const int* __restrict__ dst, int* __restrict__ cnt, int E){
    int e = blockIdx.x*blockDim.x + threadIdx.x;
    if (e < E) atomicAdd(&cnt[dst[e]], 1);
}

__global__ void k_scan(const int* __restrict__ cnt, int* __restrict__ offs,
                       int* __restrict__ cur){   // 1 block, 1024 threads, n = 4096
    __shared__ int sh[1024];
    int tid = threadIdx.x;
    int base = tid*4;
    int v0 = cnt[base], v1 = cnt[base+1], v2 = cnt[base+2], v3 = cnt[base+3];
    int sum = v0+v1+v2+v3;
    sh[tid] = sum; __syncthreads();
    for (int off = 1; off < 1024; off <<= 1){
        int t = (tid >= off) ? sh[tid-off] : 0;
        __syncthreads();
        sh[tid] += t;
        __syncthreads();
    }
    int run = sh[tid] - sum;
    offs[base] = run;   cur[base]   = run; run += v0;
    offs[base+1] = run; cur[base+1] = run; run += v1;
    offs[base+2] = run; cur[base+2] = run; run += v2;
    offs[base+3] = run; cur[base+3] = run; run += v3;
    if (tid == 1023) offs[NSENT] = run;
}

__global__ void k_scatter(const int* __restrict__ dst, int* __restrict__ cur,
                          int* __restrict__ eidx, int E){
    int e = blockIdx.x*blockDim.x + threadIdx.x;
    if (e < E) eidx[atomicAdd(&cur[dst[e]], 1)] = e;
}

// ---------------- per-dst aggregation (raw features, weighted by alpha) ----------------
// G[d,h,c] = sum_{e in dst d} alpha[e,h] * X[src_e, c]
template<int D, int COLS>
__global__ void k_agg(const float* __restrict__ X, const int* __restrict__ src,
                      const int* __restrict__ eidx, const int* __restrict__ offs,
                      const float* __restrict__ alpha, float* __restrict__ G){
    int d = blockIdx.x, tid = threadIdx.x;
    float acc[COLS][8];
    #pragma unroll
    for (int ci = 0; ci < COLS; ci++)
        #pragma unroll
        for (int h = 0; h < 8; h++) acc[ci][h] = 0.f;
    int beg = offs[d], end = offs[d+1];
    for (int i = beg; i < end; i++){
        int e = eidx[i];
        int s = src[e];
        float a[8];
        #pragma unroll
        for (int h = 0; h < 8; h++) a[h] = __ldg(&alpha[e*8+h]);
        #pragma unroll
        for (int ci = 0; ci < COLS; ci++){
            int c = tid + ci*256;
            if (c < D){
                float x = __ldg(&X[(long)s*D + c]);
                #pragma unroll
                for (int h = 0; h < 8; h++) acc[ci][h] = fmaf(a[h], x, acc[ci][h]);
            }
        }
    }
    #pragma unroll
    for (int ci = 0; ci < COLS; ci++){
        int c = tid + ci*256;
        if (c < D){
            #pragma unroll
            for (int h = 0; h < 8; h++)
                G[((long)d*8 + h)*D + c] = acc[ci][h];
        }
    }
}

// ---------------- SGEMM 128x128x16, 8x8 microtile, fused epilogues ----------------
#define BM 128
#define BN 128
#define BK 16
enum { EPI_BIAS_ELU = 0, EPI_BIAS_RELU, EPI_FUSION, EPI_RESID };

template<int EPI>
__global__ __launch_bounds__(256,2)
void gemm_k(const float* __restrict__ A, const float* __restrict__ A2, int ksplit,
            const float* __restrict__ B, float* __restrict__ C,
            const float* __restrict__ bias,
            const float* __restrict__ E0, const float* __restrict__ E1,
            int M, int N, int K, int lda, int ldb, int ldc,
            long sA, long sB, long sC, int sBias){
    int z = blockIdx.z;
    A  += (long)z*sA;  A2 += (long)z*sA;
    B  += (long)z*sB;  C  += (long)z*sC;
    const float* bp = bias + (long)z*sBias;

    __shared__ float As[BK][BM];
    __shared__ float Bs[BK][BN];
    int tid = threadIdx.x;
    int bRow = blockIdx.y*BM, bCol = blockIdx.x*BN;
    int aRow = tid >> 2, aCol = (tid & 3) << 2;
    int bR   = tid >> 5, bC   = (tid & 31) << 2;
    int tr = (tid >> 4) << 3, tc = (tid & 15) << 3;

    float acc[8][8];
    #pragma unroll
    for (int i = 0; i < 8; i++)
        #pragma unroll
        for (int j = 0; j < 8; j++) acc[i][j] = 0.f;

    for (int k0 = 0; k0 < K; k0 += BK){
        #pragma unroll
        for (int r = 0; r < 2; r++){
            int row = aRow + r*64;
            int gk  = k0 + aCol;
            float4 v = make_float4(0.f,0.f,0.f,0.f);
            if (gk < K){
                const float* srcp = (gk < ksplit)
                    ? (A  + (long)(bRow+row)*lda + gk)
                    : (A2 + (long)(bRow+row)*lda + (gk - ksplit));
                v = *reinterpret_cast<const float4*>(srcp);
            }
            As[aCol+0][row] = v.x; As[aCol+1][row] = v.y;
            As[aCol+2][row] = v.z; As[aCol+3][row] = v.w;
        }
        #pragma unroll
        for (int r = 0; r < 2; r++){
            int row = bR + r*8;
            int gk  = k0 + row;
            float4 v = make_float4(0.f,0.f,0.f,0.f);
            if (gk < K) v = *reinterpret_cast<const float4*>(B + (long)gk*ldb + bCol + bC);
            *reinterpret_cast<float4*>(&Bs[row][bC]) = v;
        }
        __syncthreads();
        #pragma unroll
        for (int kk = 0; kk < BK; kk++){
            float4 ra0 = *reinterpret_cast<const float4*>(&As[kk][tr]);
            float4 ra1 = *reinterpret_cast<const float4*>(&As[kk][tr+4]);
            float4 rb0 = *reinterpret_cast<const float4*>(&Bs[kk][tc]);
            float4 rb1 = *reinterpret_cast<const float4*>(&Bs[kk][tc+4]);
            float ra[8] = {ra0.x,ra0.y,ra0.z,ra0.w,ra1.x,ra1.y,ra1.z,ra1.w};
            float rb[8] = {rb0.x,rb0.y,rb0.z,rb0.w,rb1.x,rb1.y,rb1.z,rb1.w};
            #pragma unroll
            for (int i = 0; i < 8; i++)
                #pragma unroll
                for (int j = 0; j < 8; j++)
                    acc[i][j] = fmaf(ra[i], rb[j], acc[i][j]);
        }
        __syncthreads();
    }

    #pragma unroll
    for (int i = 0; i < 8; i++){
        int row = bRow + tr + i;
        #pragma unroll
        for (int j = 0; j < 8; j++){
            int col = bCol + tc + j;
            long idx = (long)row*ldc + col;
            float v = acc[i][j] + bp[col];
            if (EPI == EPI_BIAS_ELU){
                C[idx] = v > 0.f ? v : (expf(v) - 1.f);
            } else if (EPI == EPI_BIAS_RELU){
                C[idx] = fmaxf(v, 0.f);
            } else if (EPI == EPI_FUSION){
                float zg = 1.f/(1.f + expf(-v));
                C[idx] = zg*E0[idx] + (1.f - zg)*E1[idx];
            } else { // EPI_RESID
                C[idx] = E0[idx] + v;
            }
        }
    }
}

// ---------------- host ----------------
#define SYMF(name, sym) float* name; cudaGetSymbolAddress((void**)&name, sym)
#define SYMI(name, sym) int*   name; cudaGetSymbolAddress((void**)&name, sym)

extern "C" void kernel_launch(void* const* d_in, const int* in_sizes, int n_in,
                              void* d_out, int out_size){
    const float* Hs    = (const float*)d_in[0];
    const float* Hw    = (const float*)d_in[1];
    const float* HSc   = (const float*)d_in[2];
    const int*   w2s   = (const int*)d_in[3];
    const int*   s2s   = (const int*)d_in[4];
    const int*   S2s   = (const int*)d_in[5];
    const float* Ww_src= (const float*)d_in[6];
    const float* Ww_dst= (const float*)d_in[7];
    const float* aw_src= (const float*)d_in[8];
    const float* aw_dst= (const float*)d_in[9];
    const float* bw    = (const float*)d_in[10];
    const float* Ws    = (const float*)d_in[11];
    const float* as_src= (const float*)d_in[12];
    const float* as_dst= (const float*)d_in[13];
    const float* bs    = (const float*)d_in[14];
    const float* WS_src= (const float*)d_in[15];
    const float* WS_dst= (const float*)d_in[16];
    const float* aS_src= (const float*)d_in[17];
    const float* aS_dst= (const float*)d_in[18];
    const float* bS    = (const float*)d_in[19];
    const float* Wf1   = (const float*)d_in[20];
    const float* bf1   = (const float*)d_in[21];
    const float* Wf2   = (const float*)d_in[22];
    const float* bf2   = (const float*)d_in[23];
    const float* W1    = (const float*)d_in[24];
    const float* b1    = (const float*)d_in[25];
    const float* W2    = (const float*)d_in[26];
    const float* b2    = (const float*)d_in[27];
    float* out = (float*)d_out;

    SYMF(Uw, g_Uw); SYMF(Us, g_Us); SYMF(USec, g_USec); SYMF(U1, g_U1); SYMF(U2, g_U2);
    SYMF(Gw, g_Gw); SYMF(Gs, g_Gs); SYMF(GS, g_GS); SYMF(Hh, g_Hh);
    SYMF(Pws, g_Pws); SYMF(Pwd, g_Pwd); SYMF(Pss, g_Pss); SYMF(Psd, g_Psd);
    SYMF(PSs, g_PSs); SYMF(PSd, g_PSd);
    SYMF(alws, g_alws); SYMF(alwd, g_alwd); SYMF(alss, g_alss); SYMF(alsd, g_alsd);
    SYMF(alSs, g_alSs); SYMF(alSd, g_alSd);
    SYMF(aw, g_aw); SYMF(as, g_as); SYMF(aS, g_aS);
    SYMI(mw, g_mw); SYMI(ms, g_ms); SYMI(mS, g_mS);
    SYMF(dw, g_dw); SYMF(ds, g_ds); SYMF(dS, g_dS);
    SYMI(cw, g_cw); SYMI(cs, g_cs); SYMI(cS, g_cS);
    SYMI(ow, g_ow); SYMI(os_, g_os); SYMI(oS, g_oS);
    SYMI(uw, g_uw); SYMI(us, g_us); SYMI(uS, g_uS);
    SYMI(ew, g_ew); SYMI(es, g_es); SYMI(eS, g_eS);

    const int* src_w = w2s;            const int* dst_w = w2s + EW;
    const int* src_s = s2s;            const int* dst_s = s2s + ES;
    const int* src_S = S2s;            const int* dst_S = S2s + ESEC;

    // init
    k_init_all<<<(NSENT*8+255)/256, 256>>>(mw, dw, cw, ms, ds, cs, mS, dS, cS);

    // per-head attention projection vectors
    k_P<<<300, 256>>>(Ww_src, aw_src, Pws, 300);
    k_P<<<640, 256>>>(Ww_dst, aw_dst, Pwd, 640);
    k_P<<<640, 256>>>(Ws,     as_src, Pss, 640);
    k_P<<<640, 256>>>(Ws,     as_dst, Psd, 640);
    k_P<<<512, 256>>>(WS_src, aS_src, PSs, 512);
    k_P<<<640, 256>>>(WS_dst, aS_dst, PSd, 640);

    // attention logits per node
    k_xp<<<NWORD/8, 256>>>(Hw,  Pws, alws, NWORD, 300);
    k_xp<<<NSENT/8, 256>>>(Hs,  Pwd, alwd, NSENT, 640);
    k_xp<<<NSENT/8, 256>>>(Hs,  Pss, alss, NSENT, 640);
    k_xp<<<NSENT/8, 256>>>(Hs,  Psd, alsd, NSENT, 640);
    k_xp<<<NSEC/8,  256>>>(HSc, PSs, alSs, NSEC,  512);
    k_xp<<<NSENT/8, 256>>>(Hs,  PSd, alSd, NSENT, 640);

    // CSR build
    k_count<<<EW/256, 256>>>(dst_w, cw, EW);
    k_count<<<ES/256, 256>>>(dst_s, cs, ES);
    k_count<<<ESEC/256, 256>>>(dst_S, cS, ESEC);
    k_scan<<<1, 1024>>>(cw, ow, uw);
    k_scan<<<1, 1024>>>(cs, os_, us);
    k_scan<<<1, 1024>>>(cS, oS, uS);
    k_scatter<<<EW/256, 256>>>(dst_w, uw, ew, EW);
    k_scatter<<<ES/256, 256>>>(dst_s, us, es, ES);
    k_scatter<<<ESEC/256, 256>>>(dst_S, uS, eS, ESEC);

    // edge softmax
    k_logits<<<EW/256, 256>>>(src_w, dst_w, alws, alwd, aw, mw, EW);
    k_logits<<<ES/256, 256>>>(src_s, dst_s, alss, alsd, as, ms, ES);
    k_logits<<<ESEC/256, 256>>>(src_S, dst_S, alSs, alSd, aS, mS, ESEC);
    k_exp<<<EW/256, 256>>>(dst_w, aw, mw, dw, EW);
    k_exp<<<ES/256, 256>>>(dst_s, as, ms, ds, ES);
    k_exp<<<ESEC/256, 256>>>(dst_S, aS, mS, dS, ESEC);
    k_alpha<<<EW/256, 256>>>(dst_w, aw, dw, EW);
    k_alpha<<<ES/256, 256>>>(dst_s, as, ds, ES);
    k_alpha<<<ESEC/256, 256>>>(dst_S, aS, dS, ESEC);

    // aggregate raw features per (dst, head)
    k_agg<300,2><<<NSENT, 256>>>(Hw,  src_w, ew, ow,  aw, Gw);
    k_agg<640,3><<<NSENT, 256>>>(Hs,  src_s, es, os_, as, Gs);
    k_agg<512,2><<<NSENT, 256>>>(HSc, src_S, eS, oS,  aS, GS);

    // per-head projection + bias + ELU   (batched over heads via blockIdx.z)
    dim3 gp(CDIM/BN, NSENT/BM, 8);
    gemm_k<EPI_BIAS_ELU><<<gp, 256>>>(Gw, Gw, 300, Ww_src, Uw,  bw, nullptr, nullptr,
                                      NSENT, CDIM, 300, 8*300, HC, HC, 300, 640, 640, 640);
    gemm_k<EPI_BIAS_ELU><<<gp, 256>>>(Gs, Gs, 640, Ws,     Us,  bs, nullptr, nullptr,
                                      NSENT, CDIM, 640, 8*640, HC, HC, 640, 640, 640, 640);
    gemm_k<EPI_BIAS_ELU><<<gp, 256>>>(GS, GS, 512, WS_src, USec, bS, nullptr, nullptr,
                                      NSENT, CDIM, 512, 8*512, HC, HC, 512, 640, 640, 640);

    // fusion gates: single GEMM with implicit concat (A-split), fused sigmoid-gate epilogue
    dim3 gf(HC/BN, NSENT/BM, 1);
    gemm_k<EPI_FUSION><<<gf, 256>>>(Uw, Us, HC, Wf1, U1, bf1, Uw, Us,
                                    NSENT, HC, 2*HC, HC, HC, HC, 0, 0, 0, 0);
    gemm_k<EPI_FUSION><<<gf, 256>>>(U1, USec, HC, Wf2, U2, bf2, U1, USec,
                                    NSENT, HC, 2*HC, HC, HC, HC, 0, 0, 0, 0);

    // FFN + residual
    dim3 g1(CDIM/BN, NSENT/BM, 1);
    gemm_k<EPI_BIAS_RELU><<<g1, 256>>>(U2, U2, HC, W1, Hh, b1, nullptr, nullptr,
                                       NSENT, CDIM, HC, HC, CDIM, CDIM, 0, 0, 0, 0);
    gemm_k<EPI_RESID><<<g1, 256>>>(Hh, Hh, CDIM, W2, out, b2, Hs, nullptr,
                                   NSENT, CDIM, CDIM, CDIM, CDIM, CDIM, 0, 0, 0, 0);
}

// round 4
// speedup vs baseline: 1.9600x; 1.9592x over previous
#include <cuda_runtime.h>
#include <math.h>

#define NSENT 4096
#define NWORD 65536
#define NSEC  512
#define NHEAD 8
#define CDIM  640
#define HC    5120
#define EW    65536
#define ES    32768
#define ESEC  4096
#define NEG_SLOPE 0.2f

// ---------------- scratch (__device__ globals, no allocation) ----------------
__device__ float g_Uw[NSENT*HC];
__device__ float g_Us[NSENT*HC];
__device__ float g_USec[NSENT*HC];
__device__ float g_U1[NSENT*HC];
__device__ float g_U2[NSENT*HC];
__device__ float g_Gw[NSENT*NHEAD*300];
__device__ float g_Gs[NSENT*NHEAD*640];
__device__ float g_GS[NSENT*NHEAD*512];
__device__ float g_Hh[NSENT*640];
__device__ float g_Pws[300*8], g_Pwd[640*8], g_Pss[640*8], g_Psd[640*8], g_PSs[512*8], g_PSd[640*8];
__device__ float g_alws[NWORD*8];
__device__ float g_alwd[NSENT*8], g_alss[NSENT*8], g_alsd[NSENT*8], g_alSd[NSENT*8];
__device__ float g_alSs[NSEC*8];
__device__ float g_aw[EW*8], g_as[ES*8], g_aS[ESEC*8];   // logits -> ex -> alpha, in place
__device__ int   g_mw[NSENT*8], g_ms[NSENT*8], g_mS[NSENT*8];
__device__ float g_dw[NSENT*8], g_ds[NSENT*8], g_dS[NSENT*8];
__device__ int   g_cw[NSENT], g_cs[NSENT], g_cS[NSENT];
__device__ int   g_ow[NSENT+1], g_os[NSENT+1], g_oS[NSENT+1];
__device__ int   g_uw[NSENT], g_us[NSENT], g_uS[NSENT];
__device__ int   g_ew[EW], g_es[ES], g_eS[ESEC];

// ---------------- helpers ----------------
__device__ __forceinline__ int f2oi(float f){ int i=__float_as_int(f); return i>=0? i : (i ^ 0x7fffffff); }
__device__ __forceinline__ float oi2f(int i){ return __int_as_float(i>=0? i : (i ^ 0x7fffffff)); }
__device__ __forceinline__ unsigned f2tf(float f){
    unsigned u; asm("cvt.rna.tf32.f32 %0, %1;" : "=r"(u) : "f"(f)); return u;
}

// ---------------- init (all three graphs in one launch) ----------------
__global__ void k_init_all(int* m0, float* d0, int* c0,
                           int* m1, float* d1, int* c1,
                           int* m2, float* d2, int* c2){
    int i = blockIdx.x*blockDim.x + threadIdx.x;
    if (i < NSENT*8){
        m0[i] = (int)0x807FFFFF; d0[i] = 0.f;
        m1[i] = (int)0x807FFFFF; d1[i] = 0.f;
        m2[i] = (int)0x807FFFFF; d2[i] = 0.f;
    }
    if (i < NSENT){ c0[i] = 0; c1[i] = 0; c2[i] = 0; }
}

// P[d,h] = sum_c W[d, h*640+c] * a[h,c]   (one warp per (d,h))
__global__ void k_P(const float* __restrict__ W, const float* __restrict__ a,
                    float* __restrict__ P, int D){
    int gw   = (blockIdx.x*blockDim.x + threadIdx.x) >> 5;
    int lane = threadIdx.x & 31;
    if (gw >= D*8) return;
    int d = gw >> 3, h = gw & 7;
    const float* wr = W + (long)d*HC + h*CDIM;
    const float* ar = a + h*CDIM;
    float acc = 0.f;
    for (int c = lane; c < CDIM; c += 32) acc = fmaf(__ldg(&wr[c]), __ldg(&ar[c]), acc);
    #pragma unroll
    for (int o = 16; o; o >>= 1) acc += __shfl_xor_sync(0xffffffffu, acc, o);
    if (!lane) P[gw] = acc;
}

// AL[n,h] = sum_d X[n,d]*P[d,h]   (one warp per row)
__global__ void k_xp(const float* __restrict__ X, const float* __restrict__ P,
                     float* __restrict__ AL, int N, int D){
    int row  = (blockIdx.x*blockDim.x + threadIdx.x) >> 5;
    int lane = threadIdx.x & 31;
    if (row >= N) return;
    const float* x = X + (long)row*D;
    float acc[8] = {0,0,0,0,0,0,0,0};
    for (int dd = lane; dd < D; dd += 32){
        float xv = __ldg(&x[dd]);
        const float* p = P + dd*8;
        #pragma unroll
        for (int h = 0; h < 8; h++) acc[h] = fmaf(xv, __ldg(&p[h]), acc[h]);
    }
    #pragma unroll
    for (int h = 0; h < 8; h++){
        #pragma unroll
        for (int o = 16; o; o >>= 1) acc[h] += __shfl_xor_sync(0xffffffffu, acc[h], o);
    }
    if (lane == 0){
        #pragma unroll
        for (int h = 0; h < 8; h++) AL[(long)row*8 + h] = acc[h];
    }
}

// ---------------- edge softmax ----------------
__global__ void k_logits(const int* __restrict__ src, const int* __restrict__ dst,
                         const float* __restrict__ als, const float* __restrict__ ald,
                         float* __restrict__ lg, int* __restrict__ segmax, int E){
    int e = blockIdx.x*blockDim.x + threadIdx.x;
    if (e >= E) return;
    int s = src[e], d = dst[e];
    #pragma unroll
    for (int h = 0; h < 8; h++){
        float v = __ldg(&als[s*8+h]) + __ldg(&ald[d*8+h]);
        v = v > 0.f ? v : NEG_SLOPE*v;
        lg[e*8+h] = v;
        atomicMax(&segmax[d*8+h], f2oi(v));
    }
}

__global__ void k_exp(const int* __restrict__ dst, float* __restrict__ lg,
                      const int* __restrict__ segmax, float* __restrict__ den, int E){
    int e = blockIdx.x*blockDim.x + threadIdx.x;
    if (e >= E) return;
    int d = dst[e];
    #pragma unroll
    for (int h = 0; h < 8; h++){
        float m  = oi2f(__ldg(&segmax[d*8+h]));
        float ex = expf(lg[e*8+h] - m);
        lg[e*8+h] = ex;
        atomicAdd(&den[d*8+h], ex);
    }
}

__global__ void k_alpha(const int* __restrict__ dst, float* __restrict__ lg,
                        const float* __restrict__ den, int E){
    int e = blockIdx.x*blockDim.x + threadIdx.x;
    if (e >= E) return;
    int d = dst[e];
    #pragma unroll
    for (int h = 0; h < 8; h++)
        lg[e*8+h] = lg[e*8+h] / (__ldg(&den[d*8+h]) + 1e-16f);
}

// ---------------- CSR build ----------------
__global__ void k_count(const int* __restrict__ dst, int* __restrict__ cnt, int E){
    int e = blockIdx.x*blockDim.x + threadIdx.x;
    if (e < E) atomicAdd(&cnt[dst[e]], 1);
}

__global__ void k_scan(const int* __restrict__ cnt, int* __restrict__ offs,
                       int* __restrict__ cur){   // 1 block, 1024 threads, n = 4096
    __shared__ int sh[1024];
    int tid = threadIdx.x;
    int base = tid*4;
    int v0 = cnt[base], v1 = cnt[base+1], v2 = cnt[base+2], v3 = cnt[base+3];
    int sum = v0+v1+v2+v3;
    sh[tid] = sum; __syncthreads();
    for (int off = 1; off < 1024; off <<= 1){
        int t = (tid >= off) ? sh[tid-off] : 0;
        __syncthreads();
        sh[tid] += t;
        __syncthreads();
    }
    int run = sh[tid] - sum;
    offs[base] = run;   cur[base]   = run; run += v0;
    offs[base+1] = run; cur[base+1] = run; run += v1;
    offs[base+2] = run; cur[base+2] = run; run += v2;
    offs[base+3] = run; cur[base+3] = run; run += v3;
    if (tid == 1023) offs[NSENT] = run;
}

__global__ void k_scatter(const int* __restrict__ dst, int* __restrict__ cur,
                          int* __restrict__ eidx, int E){
    int e = blockIdx.x*blockDim.x + threadIdx.x;
    if (e < E) eidx[atomicAdd(&cur[dst[e]], 1)] = e;
}

// ---------------- per-dst aggregation (raw features, weighted by alpha) ----------------
template<int D, int COLS>
__global__ void k_agg(const float* __restrict__ X, const int* __restrict__ src,
                      const int* __restrict__ eidx, const int* __restrict__ offs,
                      const float* __restrict__ alpha, float* __restrict__ G){
    int d = blockIdx.x, tid = threadIdx.x;
    float acc[COLS][8];
    #pragma unroll
    for (int ci = 0; ci < COLS; ci++)
        #pragma unroll
        for (int h = 0; h < 8; h++) acc[ci][h] = 0.f;
    int beg = offs[d], end = offs[d+1];
    for (int i = beg; i < end; i++){
        int e = eidx[i];
        int s = src[e];
        float a[8];
        #pragma unroll
        for (int h = 0; h < 8; h++) a[h] = __ldg(&alpha[e*8+h]);
        #pragma unroll
        for (int ci = 0; ci < COLS; ci++){
            int c = tid + ci*256;
            if (c < D){
                float x = __ldg(&X[(long)s*D + c]);
                #pragma unroll
                for (int h = 0; h < 8; h++) acc[ci][h] = fmaf(a[h], x, acc[ci][h]);
            }
        }
    }
    #pragma unroll
    for (int ci = 0; ci < COLS; ci++){
        int c = tid + ci*256;
        if (c < D){
            #pragma unroll
            for (int h = 0; h < 8; h++)
                G[((long)d*8 + h)*D + c] = acc[ci][h];
        }
    }
}

// ---------------- TF32 tensor-core GEMM 128x128x16, mma.sync m16n8k8 ----------------
#define BM 128
#define BN 128
#define BK 16
#define ASTR 137   // As row stride (floats): conflict-free frag loads & staging stores
#define BSTR 136   // Bs row stride (floats): 16B-aligned float4 staging, conflict-free frags
enum { EPI_BIAS_ELU = 0, EPI_BIAS_RELU, EPI_FUSION, EPI_RESID };

__device__ __forceinline__ void mma_tf32(float* d, const unsigned* a, const unsigned* b){
    asm volatile(
        "mma.sync.aligned.m16n8k8.row.col.f32.tf32.tf32.f32 "
        "{%0,%1,%2,%3}, {%4,%5,%6,%7}, {%8,%9}, {%0,%1,%2,%3};"
        : "+f"(d[0]), "+f"(d[1]), "+f"(d[2]), "+f"(d[3])
        : "r"(a[0]), "r"(a[1]), "r"(a[2]), "r"(a[3]), "r"(b[0]), "r"(b[1]));
}

template<int EPI>
__global__ __launch_bounds__(256,2)
void gemm_k(const float* __restrict__ A, const float* __restrict__ A2, int ksplit,
            const float* __restrict__ B, float* __restrict__ C,
            const float* __restrict__ bias,
            const float* __restrict__ E0, const float* __restrict__ E1,
            int M, int N, int K, int lda, int ldb, int ldc,
            long sA, long sB, long sC, int sBias){
    int z = blockIdx.z;
    A  += (long)z*sA;  A2 += (long)z*sA;
    B  += (long)z*sB;  C  += (long)z*sC;
    const float* bp = bias + (long)z*sBias;

    __shared__ unsigned As[BK*ASTR];
    __shared__ unsigned Bs[BK*BSTR];
    int tid  = threadIdx.x;
    int wid  = tid >> 5, lane = tid & 31;
    int g    = lane >> 2, tig = lane & 3;
    int wm   = wid & 3, wn = wid >> 2;          // warp tile: 32 (M) x 64 (N)
    int m0   = wm*32, n0 = wn*64;
    int bRow = blockIdx.y*BM, bCol = blockIdx.x*BN;
    int aRow = tid >> 2, aCol = (tid & 3) << 2; // A staging: 2 rows (aRow, aRow+64), 4 k each
    int bR   = tid >> 5, bC   = (tid & 31) << 2;// B staging: rows bR, bR+8, float4 cols

    float acc[2][8][4];
    #pragma unroll
    for (int mi = 0; mi < 2; mi++)
        #pragma unroll
        for (int j = 0; j < 8; j++)
            #pragma unroll
            for (int c = 0; c < 4; c++) acc[mi][j][c] = 0.f;

    float4 pa[2], pb[2];
    // prefetch tile 0
    {
        int k0 = 0;
        #pragma unroll
        for (int r = 0; r < 2; r++){
            int gk = k0 + aCol;
            pa[r] = make_float4(0.f,0.f,0.f,0.f);
            if (gk < K){
                const float* sp = (gk < ksplit)
                    ? (A  + (long)(bRow + aRow + r*64)*lda + gk)
                    : (A2 + (long)(bRow + aRow + r*64)*lda + (gk - ksplit));
                pa[r] = *reinterpret_cast<const float4*>(sp);
            }
            int gkb = k0 + bR + r*8;
            pb[r] = make_float4(0.f,0.f,0.f,0.f);
            if (gkb < K) pb[r] = *reinterpret_cast<const float4*>(B + (long)gkb*ldb + bCol + bC);
        }
    }

    for (int k0 = 0; k0 < K; k0 += BK){
        // stage (fp32 -> tf32)
        #pragma unroll
        for (int r = 0; r < 2; r++){
            int row = aRow + r*64;
            As[(aCol+0)*ASTR + row] = f2tf(pa[r].x);
            As[(aCol+1)*ASTR + row] = f2tf(pa[r].y);
            As[(aCol+2)*ASTR + row] = f2tf(pa[r].z);
            As[(aCol+3)*ASTR + row] = f2tf(pa[r].w);
            unsigned* bw = &Bs[(bR + r*8)*BSTR + bC];
            bw[0] = f2tf(pb[r].x); bw[1] = f2tf(pb[r].y);
            bw[2] = f2tf(pb[r].z); bw[3] = f2tf(pb[r].w);
        }
        __syncthreads();

        // prefetch next tile
        if (k0 + BK < K){
            int kn = k0 + BK;
            #pragma unroll
            for (int r = 0; r < 2; r++){
                int gk = kn + aCol;
                pa[r] = make_float4(0.f,0.f,0.f,0.f);
                if (gk < K){
                    const float* sp = (gk < ksplit)
                        ? (A  + (long)(bRow + aRow + r*64)*lda + gk)
                        : (A2 + (long)(bRow + aRow + r*64)*lda + (gk - ksplit));
                    pa[r] = *reinterpret_cast<const float4*>(sp);
                }
                int gkb = kn + bR + r*8;
                pb[r] = make_float4(0.f,0.f,0.f,0.f);
                if (gkb < K) pb[r] = *reinterpret_cast<const float4*>(B + (long)gkb*ldb + bCol + bC);
            }
        }

        // compute: 2 x k8 steps
        #pragma unroll
        for (int ks = 0; ks < 2; ks++){
            int kk = ks*8;
            unsigned af[2][4];
            #pragma unroll
            for (int mi = 0; mi < 2; mi++){
                int mb = m0 + mi*16;
                af[mi][0] = As[(kk+tig  )*ASTR + mb + g    ];
                af[mi][1] = As[(kk+tig  )*ASTR + mb + g + 8];
                af[mi][2] = As[(kk+tig+4)*ASTR + mb + g    ];
                af[mi][3] = As[(kk+tig+4)*ASTR + mb + g + 8];
            }
            #pragma unroll
            for (int j = 0; j < 8; j++){
                unsigned bf[2];
                bf[0] = Bs[(kk+tig  )*BSTR + n0 + j*8 + g];
                bf[1] = Bs[(kk+tig+4)*BSTR + n0 + j*8 + g];
                mma_tf32(acc[0][j], af[0], bf);
                mma_tf32(acc[1][j], af[1], bf);
            }
        }
        __syncthreads();
    }

    // epilogue: thread owns rows (m0+mi*16+g, +8), cols (n0+j*8+tig*2, +1)
    #pragma unroll
    for (int mi = 0; mi < 2; mi++){
        #pragma unroll
        for (int half = 0; half < 2; half++){
            int row = bRow + m0 + mi*16 + g + half*8;
            #pragma unroll
            for (int j = 0; j < 8; j++){
                int col = bCol + n0 + j*8 + tig*2;
                long idx = (long)row*ldc + col;
                float v0 = acc[mi][j][half*2+0] + bp[col];
                float v1 = acc[mi][j][half*2+1] + bp[col+1];
                float r0, r1;
                if (EPI == EPI_BIAS_ELU){
                    r0 = v0 > 0.f ? v0 : (expf(v0) - 1.f);
                    r1 = v1 > 0.f ? v1 : (expf(v1) - 1.f);
                } else if (EPI == EPI_BIAS_RELU){
                    r0 = fmaxf(v0, 0.f);
                    r1 = fmaxf(v1, 0.f);
                } else if (EPI == EPI_FUSION){
                    float z0 = 1.f/(1.f + expf(-v0));
                    float z1 = 1.f/(1.f + expf(-v1));
                    r0 = z0*E0[idx]   + (1.f - z0)*E1[idx];
                    r1 = z1*E0[idx+1] + (1.f - z1)*E1[idx+1];
                } else { // EPI_RESID
                    r0 = E0[idx]   + v0;
                    r1 = E0[idx+1] + v1;
                }
                *reinterpret_cast<float2*>(&C[idx]) = make_float2(r0, r1);
            }
        }
    }
}

// ---------------- host ----------------
#define SYMF(name, sym) float* name; cudaGetSymbolAddress((void**)&name, sym)
#define SYMI(name, sym) int*   name; cudaGetSymbolAddress((void**)&name, sym)

extern "C" void kernel_launch(void* const* d_in, const int* in_sizes, int n_in,
                              void* d_out, int out_size){
    const float* Hs    = (const float*)d_in[0];
    const float* Hw    = (const float*)d_in[1];
    const float* HSc   = (const float*)d_in[2];
    const int*   w2s   = (const int*)d_in[3];
    const int*   s2s   = (const int*)d_in[4];
    const int*   S2s   = (const int*)d_in[5];
    const float* Ww_src= (const float*)d_in[6];
    const float* Ww_dst= (const float*)d_in[7];
    const float* aw_src= (const float*)d_in[8];
    const float* aw_dst= (const float*)d_in[9];
    const float* bw    = (const float*)d_in[10];
    const float* Ws    = (const float*)d_in[11];
    const float* as_src= (const float*)d_in[12];
    const float* as_dst= (const float*)d_in[13];
    const float* bs    = (const float*)d_in[14];
    const float* WS_src= (const float*)d_in[15];
    const float* WS_dst= (const float*)d_in[16];
    const float* aS_src= (const float*)d_in[17];
    const float* aS_dst= (const float*)d_in[18];
    const float* bS    = (const float*)d_in[19];
    const float* Wf1   = (const float*)d_in[20];
    const float* bf1   = (const float*)d_in[21];
    const float* Wf2   = (const float*)d_in[22];
    const float* bf2   = (const float*)d_in[23];
    const float* W1    = (const float*)d_in[24];
    const float* b1    = (const float*)d_in[25];
    const float* W2    = (const float*)d_in[26];
    const float* b2    = (const float*)d_in[27];
    float* out = (float*)d_out;

    SYMF(Uw, g_Uw); SYMF(Us, g_Us); SYMF(USec, g_USec); SYMF(U1, g_U1); SYMF(U2, g_U2);
    SYMF(Gw, g_Gw); SYMF(Gs, g_Gs); SYMF(GS, g_GS); SYMF(Hh, g_Hh);
    SYMF(Pws, g_Pws); SYMF(Pwd, g_Pwd); SYMF(Pss, g_Pss); SYMF(Psd, g_Psd);
    SYMF(PSs, g_PSs); SYMF(PSd, g_PSd);
    SYMF(alws, g_alws); SYMF(alwd, g_alwd); SYMF(alss, g_alss); SYMF(alsd, g_alsd);
    SYMF(alSs, g_alSs); SYMF(alSd, g_alSd);
    SYMF(aw, g_aw); SYMF(as, g_as); SYMF(aS, g_aS);
    SYMI(mw, g_mw); SYMI(ms, g_ms); SYMI(mS, g_mS);
    SYMF(dw, g_dw); SYMF(ds, g_ds); SYMF(dS, g_dS);
    SYMI(cw, g_cw); SYMI(cs, g_cs); SYMI(cS, g_cS);
    SYMI(ow, g_ow); SYMI(os_, g_os); SYMI(oS, g_oS);
    SYMI(uw, g_uw); SYMI(us, g_us); SYMI(uS, g_uS);
    SYMI(ew, g_ew); SYMI(es, g_es); SYMI(eS, g_eS);

    const int* src_w = w2s;            const int* dst_w = w2s + EW;
    const int* src_s = s2s;            const int* dst_s = s2s + ES;
    const int* src_S = S2s;            const int* dst_S = S2s + ESEC;

    // init
    k_init_all<<<(NSENT*8+255)/256, 256>>>(mw, dw, cw, ms, ds, cs, mS, dS, cS);

    // per-head attention projection vectors
    k_P<<<300, 256>>>(Ww_src, aw_src, Pws, 300);
    k_P<<<640, 256>>>(Ww_dst, aw_dst, Pwd, 640);
    k_P<<<640, 256>>>(Ws,     as_src, Pss, 640);
    k_P<<<640, 256>>>(Ws,     as_dst, Psd, 640);
    k_P<<<512, 256>>>(WS_src, aS_src, PSs, 512);
    k_P<<<640, 256>>>(WS_dst, aS_dst, PSd, 640);

    // attention logits per node
    k_xp<<<NWORD/8, 256>>>(Hw,  Pws, alws, NWORD, 300);
    k_xp<<<NSENT/8, 256>>>(Hs,  Pwd, alwd, NSENT, 640);
    k_xp<<<NSENT/8, 256>>>(Hs,  Pss, alss, NSENT, 640);
    k_xp<<<NSENT/8, 256>>>(Hs,  Psd, alsd, NSENT, 640);
    k_xp<<<NSEC/8,  256>>>(HSc, PSs, alSs, NSEC,  512);
    k_xp<<<NSENT/8, 256>>>(Hs,  PSd, alSd, NSENT, 640);

    // CSR build
    k_count<<<EW/256, 256>>>(dst_w, cw, EW);
    k_count<<<ES/256, 256>>>(dst_s, cs, ES);
    k_count<<<ESEC/256, 256>>>(dst_S, cS, ESEC);
    k_scan<<<1, 1024>>>(cw, ow, uw);
    k_scan<<<1, 1024>>>(cs, os_, us);
    k_scan<<<1, 1024>>>(cS, oS, uS);
    k_scatter<<<EW/256, 256>>>(dst_w, uw, ew, EW);
    k_scatter<<<ES/256, 256>>>(dst_s, us, es, ES);
    k_scatter<<<ESEC/256, 256>>>(dst_S, uS, eS, ESEC);

    // edge softmax
    k_logits<<<EW/256, 256>>>(src_w, dst_w, alws, alwd, aw, mw, EW);
    k_logits<<<ES/256, 256>>>(src_s, dst_s, alss, alsd, as, ms, ES);
    k_logits<<<ESEC/256, 256>>>(src_S, dst_S, alSs, alSd, aS, mS, ESEC);
    k_exp<<<EW/256, 256>>>(dst_w, aw, mw, dw, EW);
    k_exp<<<ES/256, 256>>>(dst_s, as, ms, ds, ES);
    k_exp<<<ESEC/256, 256>>>(dst_S, aS, mS, dS, ESEC);
    k_alpha<<<EW/256, 256>>>(dst_w, aw, dw, EW);
    k_alpha<<<ES/256, 256>>>(dst_s, as, ds, ES);
    k_alpha<<<ESEC/256, 256>>>(dst_S, aS, dS, ESEC);

    // aggregate raw features per (dst, head)
    k_agg<300,2><<<NSENT, 256>>>(Hw,  src_w, ew, ow,  aw, Gw);
    k_agg<640,3><<<NSENT, 256>>>(Hs,  src_s, es, os_, as, Gs);
    k_agg<512,2><<<NSENT, 256>>>(HSc, src_S, eS, oS,  aS, GS);

    // per-head projection + bias + ELU   (batched over heads via blockIdx.z)
    dim3 gp(CDIM/BN, NSENT/BM, 8);
    gemm_k<EPI_BIAS_ELU><<<gp, 256>>>(Gw, Gw, 300, Ww_src, Uw,  bw, nullptr, nullptr,
                                      NSENT, CDIM, 300, 8*300, HC, HC, 300, 640, 640, 640);
    gemm_k<EPI_BIAS_ELU><<<gp, 256>>>(Gs, Gs, 640, Ws,     Us,  bs, nullptr, nullptr,
                                      NSENT, CDIM, 640, 8*640, HC, HC, 640, 640, 640, 640);
    gemm_k<EPI_BIAS_ELU><<<gp, 256>>>(GS, GS, 512, WS_src, USec, bS, nullptr, nullptr,
                                      NSENT, CDIM, 512, 8*512, HC, HC, 512, 640, 640, 640);

    // fusion gates: single GEMM with implicit concat (A-split), fused sigmoid-gate epilogue
    dim3 gf(HC/BN, NSENT/BM, 1);
    gemm_k<EPI_FUSION><<<gf, 256>>>(Uw, Us, HC, Wf1, U1, bf1, Uw, Us,
                                    NSENT, HC, 2*HC, HC, HC, HC, 0, 0, 0, 0);
    gemm_k<EPI_FUSION><<<gf, 256>>>(U1, USec, HC, Wf2, U2, bf2, U1, USec,
                                    NSENT, HC, 2*HC, HC, HC, HC, 0, 0, 0, 0);

    // FFN + residual
    dim3 g1(CDIM/BN, NSENT/BM, 1);
    gemm_k<EPI_BIAS_RELU><<<g1, 256>>>(U2, U2, HC, W1, Hh, b1, nullptr, nullptr,
                                       NSENT, CDIM, HC, HC, CDIM, CDIM, 0, 0, 0, 0);
    gemm_k<EPI_RESID><<<g1, 256>>>(Hh, Hh, CDIM, W2, out, b2, Hs, nullptr,
                                   NSENT, CDIM, CDIM, CDIM, CDIM, CDIM, 0, 0, 0, 0);
}

// round 8
// speedup vs baseline: 4.0701x; 2.0766x over previous
#include <cuda_runtime.h>
#include <cuda_fp16.h>
#include <math.h>
#include <stdint.h>

#define NSENT 4096
#define NWORD 65536
#define NSEC  512
#define NHEAD 8
#define CDIM  640
#define HC    5120
#define EW    65536
#define ES    32768
#define ESEC  4096
#define NEG_SLOPE 0.2f

// ---------------- scratch (__device__ globals, no allocation) ----------------
__device__ float g_Uw[NSENT*HC];
__device__ float g_Us[NSENT*HC];
__device__ float g_USec[NSENT*HC];
__device__ float g_U1[NSENT*HC];
__device__ float g_U2[NSENT*HC];
__device__ float g_Gw[NSENT*NHEAD*300];
__device__ float g_Gs[NSENT*NHEAD*640];
__device__ float g_GS[NSENT*NHEAD*512];
__device__ float g_Hh[NSENT*640];
__device__ float g_Pws[300*8], g_Pwd[640*8], g_Pss[640*8], g_Psd[640*8], g_PSs[512*8], g_PSd[640*8];
__device__ float g_alws[NWORD*8];
__device__ float g_alwd[NSENT*8], g_alss[NSENT*8], g_alsd[NSENT*8], g_alSd[NSENT*8];
__device__ float g_alSs[NSEC*8];
__device__ float g_aw[EW*8], g_as[ES*8], g_aS[ESEC*8];   // logits -> ex -> alpha, in place
__device__ int   g_mw[NSENT*8], g_ms[NSENT*8], g_mS[NSENT*8];
__device__ float g_dw[NSENT*8], g_ds[NSENT*8], g_dS[NSENT*8];
__device__ int   g_cw[NSENT], g_cs[NSENT], g_cS[NSENT];
__device__ int   g_ow[NSENT+1], g_os[NSENT+1], g_oS[NSENT+1];
__device__ int   g_uw[NSENT], g_us[NSENT], g_uS[NSENT];
__device__ int   g_ew[EW], g_es[ES], g_eS[ESEC];

// ---------------- helpers ----------------
__device__ __forceinline__ int f2oi(float f){ int i=__float_as_int(f); return i>=0? i : (i ^ 0x7fffffff); }
__device__ __forceinline__ float oi2f(int i){ return __int_as_float(i>=0? i : (i ^ 0x7fffffff)); }
__device__ __forceinline__ uint32_t f2h2(float a, float b){
    __half2 h = __floats2half2_rn(a, b);
    return *reinterpret_cast<uint32_t*>(&h);
}

// ---------------- init (all three graphs in one launch) ----------------
__global__ void k_init_all(int* m0, float* d0, int* c0,
                           int* m1, float* d1, int* c1,
                           int* m2, float* d2, int* c2){
    int i = blockIdx.x*blockDim.x + threadIdx.x;
    if (i < NSENT*8){
        m0[i] = (int)0x807FFFFF; d0[i] = 0.f;
        m1[i] = (int)0x807FFFFF; d1[i] = 0.f;
        m2[i] = (int)0x807FFFFF; d2[i] = 0.f;
    }
    if (i < NSENT){ c0[i] = 0; c1[i] = 0; c2[i] = 0; }
}

// P[d,h] = sum_c W[d, h*640+c] * a[h,c]   (one warp per (d,h))
__global__ void k_P(const float* __restrict__ W, const float* __restrict__ a,
                    float* __restrict__ P, int D){
    int gw   = (blockIdx.x*blockDim.x + threadIdx.x) >> 5;
    int lane = threadIdx.x & 31;
    if (gw >= D*8) return;
    int d = gw >> 3, h = gw & 7;
    const float* wr = W + (long)d*HC + h*CDIM;
    const float* ar = a + h*CDIM;
    float acc = 0.f;
    for (int c = lane; c < CDIM; c += 32) acc = fmaf(__ldg(&wr[c]), __ldg(&ar[c]), acc);
    #pragma unroll
    for (int o = 16; o; o >>= 1) acc += __shfl_xor_sync(0xffffffffu, acc, o);
    if (!lane) P[gw] = acc;
}

// AL[n,h] = sum_d X[n,d]*P[d,h]   (one warp per row)
__global__ void k_xp(const float* __restrict__ X, const float* __restrict__ P,
                     float* __restrict__ AL, int N, int D){
    int row  = (blockIdx.x*blockDim.x + threadIdx.x) >> 5;
    int lane = threadIdx.x & 31;
    if (row >= N) return;
    const float* x = X + (long)row*D;
    float acc[8] = {0,0,0,0,0,0,0,0};
    for (int dd = lane; dd < D; dd += 32){
        float xv = __ldg(&x[dd]);
        const float* p = P + dd*8;
        #pragma unroll
        for (int h = 0; h < 8; h++) acc[h] = fmaf(xv, __ldg(&p[h]), acc[h]);
    }
    #pragma unroll
    for (int h = 0; h < 8; h++){
        #pragma unroll
        for (int o = 16; o; o >>= 1) acc[h] += __shfl_xor_sync(0xffffffffu, acc[h], o);
    }
    if (lane == 0){
        #pragma unroll
        for (int h = 0; h < 8; h++) AL[(long)row*8 + h] = acc[h];
    }
}

// ---------------- edge softmax ----------------
__global__ void k_logits(const int* __restrict__ src, const int* __restrict__ dst,
                         const float* __restrict__ als, const float* __restrict__ ald,
                         float* __restrict__ lg, int* __restrict__ segmax, int E){
    int e = blockIdx.x*blockDim.x + threadIdx.x;
    if (e >= E) return;
    int s = src[e], d = dst[e];
    #pragma unroll
    for (int h = 0; h < 8; h++){
        float v = __ldg(&als[s*8+h]) + __ldg(&ald[d*8+h]);
        v = v > 0.f ? v : NEG_SLOPE*v;
        lg[e*8+h] = v;
        atomicMax(&segmax[d*8+h], f2oi(v));
    }
}
__global__ void k_exp(const int* __restrict__ dst, float* __restrict__ lg,
                      const int* __restrict__ segmax, float* __restrict__ den, int E){
    int e = blockIdx.x*blockDim.x + threadIdx.x;
    if (e >= E) return;
    int d = dst[e];
    #pragma unroll
    for (int h = 0; h < 8; h++){
        float m  = oi2f(__ldg(&segmax[d*8+h]));
        float ex = expf(lg[e*8+h] - m);
        lg[e*8+h] = ex;
        atomicAdd(&den[d*8+h], ex);
    }
}
__global__ void k_alpha(const int* __restrict__ dst, float* __restrict__ lg,
                        const float* __restrict__ den, int E){
    int e = blockIdx.x*blockDim.x + threadIdx.x;
    if (e >= E) return;
    int d = dst[e];
    #pragma unroll
    for (int h = 0; h < 8; h++)
        lg[e*8+h] = lg[e*8+h] / (__ldg(&den[d*8+h]) + 1e-16f);
}

// ---------------- CSR build ----------------
__global__ void k_count(const int* __restrict__ dst, int* __restrict__ cnt, int E){
    int e = blockIdx.x*blockDim.x + threadIdx.x;
    if (e < E) atomicAdd(&cnt[dst[e]], 1);
}
__global__ void k_scan(const int* __restrict__ cnt, int* __restrict__ offs,
                       int* __restrict__ cur){
    __shared__ int sh[1024];
    int tid = threadIdx.x;
    int base = tid*4;
    int v0 = cnt[base], v1 = cnt[base+1], v2 = cnt[base+2], v3 = cnt[base+3];
    int sum = v0+v1+v2+v3;
    sh[tid] = sum; __syncthreads();
    for (int off = 1; off < 1024; off <<= 1){
        int t = (tid >= off) ? sh[tid-off] : 0;
        __syncthreads();
        sh[tid] += t;
        __syncthreads();
    }
    int run = sh[tid] - sum;
    offs[base] = run;   cur[base]   = run; run += v0;
    offs[base+1] = run; cur[base+1] = run; run += v1;
    offs[base+2] = run; cur[base+2] = run; run += v2;
    offs[base+3] = run; cur[base+3] = run; run += v3;
    if (tid == 1023) offs[NSENT] = run;
}
__global__ void k_scatter(const int* __restrict__ dst, int* __restrict__ cur,
                          int* __restrict__ eidx, int E){
    int e = blockIdx.x*blockDim.x + threadIdx.x;
    if (e < E) eidx[atomicAdd(&cur[dst[e]], 1)] = e;
}

// ---------------- per-dst aggregation ----------------
template<int D, int COLS>
__global__ void k_agg(const float* __restrict__ X, const int* __restrict__ src,
                      const int* __restrict__ eidx, const int* __restrict__ offs,
                      const float* __restrict__ alpha, float* __restrict__ G){
    int d = blockIdx.x, tid = threadIdx.x;
    float acc[COLS][8];
    #pragma unroll
    for (int ci = 0; ci < COLS; ci++)
        #pragma unroll
        for (int h = 0; h < 8; h++) acc[ci][h] = 0.f;
    int beg = offs[d], end = offs[d+1];
    for (int i = beg; i < end; i++){
        int e = eidx[i];
        int s = src[e];
        float a[8];
        #pragma unroll
        for (int h = 0; h < 8; h++) a[h] = __ldg(&alpha[e*8+h]);
        #pragma unroll
        for (int ci = 0; ci < COLS; ci++){
            int c = tid + ci*256;
            if (c < D){
                float x = __ldg(&X[(long)s*D + c]);
                #pragma unroll
                for (int h = 0; h < 8; h++) acc[ci][h] = fmaf(a[h], x, acc[ci][h]);
            }
        }
    }
    #pragma unroll
    for (int ci = 0; ci < COLS; ci++){
        int c = tid + ci*256;
        if (c < D){
            #pragma unroll
            for (int h = 0; h < 8; h++)
                G[((long)d*8 + h)*D + c] = acc[ci][h];
        }
    }
}

// ---------------- FP16 tensor-core GEMM 128x128x16, mma.sync m16n8k16 ----------------
// As2[k2][m]: half2 packed over k, stride 136 (bank = 8*k2+m mod 32 -> conflict-free frags)
// Bs2[n][k2]: half2 packed over k, stride 9
#define BM 128
#define BN 128
#define BK 16
#define ASTR2 136
#define BSTR2 9
enum { EPI_BIAS_ELU = 0, EPI_BIAS_RELU, EPI_FUSION, EPI_RESID };

__device__ __forceinline__ void mma_f16(float* d, const uint32_t* a, const uint32_t* b){
    asm volatile(
        "mma.sync.aligned.m16n8k16.row.col.f32.f16.f16.f32 "
        "{%0,%1,%2,%3}, {%4,%5,%6,%7}, {%8,%9}, {%0,%1,%2,%3};"
        : "+f"(d[0]), "+f"(d[1]), "+f"(d[2]), "+f"(d[3])
        : "r"(a[0]), "r"(a[1]), "r"(a[2]), "r"(a[3]), "r"(b[0]), "r"(b[1]));
}

template<int EPI>
__global__ __launch_bounds__(256,2)
void gemm_k(const float* __restrict__ A, const float* __restrict__ A2, int ksplit,
            const float* __restrict__ B, float* __restrict__ C,
            const float* __restrict__ bias,
            const float* __restrict__ E0, const float* __restrict__ E1,
            int M, int N, int K, int lda, int ldb, int ldc,
            long sA, long sB, long sC, int sBias){
    int z = blockIdx.z;
    A  += (long)z*sA;  A2 += (long)z*sA;
    B  += (long)z*sB;  C  += (long)z*sC;
    const float* bp = bias + (long)z*sBias;

    __shared__ uint32_t As2[(BK/2)*ASTR2];
    __shared__ uint32_t Bs2[BN*BSTR2];
    int tid  = threadIdx.x;
    int wid  = tid >> 5, lane = tid & 31;
    int g    = lane >> 2, tig = lane & 3;
    int wm   = wid & 3, wn = wid >> 2;          // warp tile: 32 (M) x 64 (N)
    int m0   = wm*32, n0 = wn*64;
    int bRow = blockIdx.y*BM, bCol = blockIdx.x*BN;
    int aRow = tid >> 2, aCol = (tid & 3) << 2; // A: rows aRow, aRow+64; k = aCol..aCol+3
    int bR   = tid >> 5;                        // B: k2 = bR (k rows 2bR, 2bR+1)
    int bC   = (tid & 31) << 2;                 // B: 4 n columns

    float acc[2][8][4];
    #pragma unroll
    for (int mi = 0; mi < 2; mi++)
        #pragma unroll
        for (int j = 0; j < 8; j++)
            #pragma unroll
            for (int c = 0; c < 4; c++) acc[mi][j][c] = 0.f;

    float4 pa[2], pbl, pbh;
    // prefetch tile 0  (k, ksplit, K all multiples of 4 -> float4 never straddles)
    {
        #pragma unroll
        for (int r = 0; r < 2; r++){
            int gk = aCol;
            pa[r] = make_float4(0.f,0.f,0.f,0.f);
            if (gk < K){
                const float* sp = (gk < ksplit)
                    ? (A  + (long)(bRow + aRow + r*64)*lda + gk)
                    : (A2 + (long)(bRow + aRow + r*64)*lda + (gk - ksplit));
                pa[r] = *reinterpret_cast<const float4*>(sp);
            }
        }
        int k0b = 2*bR;
        pbl = make_float4(0.f,0.f,0.f,0.f);
        pbh = make_float4(0.f,0.f,0.f,0.f);
        if (k0b     < K) pbl = *reinterpret_cast<const float4*>(B + (long)(k0b  )*ldb + bCol + bC);
        if (k0b + 1 < K) pbh = *reinterpret_cast<const float4*>(B + (long)(k0b+1)*ldb + bCol + bC);
    }

    for (int k0 = 0; k0 < K; k0 += BK){
        // stage (fp32 -> half2)
        #pragma unroll
        for (int r = 0; r < 2; r++){
            int row = aRow + r*64;
            int k2 = aCol >> 1;
            As2[(k2  )*ASTR2 + row] = f2h2(pa[r].x, pa[r].y);
            As2[(k2+1)*ASTR2 + row] = f2h2(pa[r].z, pa[r].w);
        }
        {
            float bl[4] = {pbl.x, pbl.y, pbl.z, pbl.w};
            float bh[4] = {pbh.x, pbh.y, pbh.z, pbh.w};
            #pragma unroll
            for (int i = 0; i < 4; i++)
                Bs2[(bC + i)*BSTR2 + bR] = f2h2(bl[i], bh[i]);
        }
        __syncthreads();

        // prefetch next tile
        if (k0 + BK < K){
            int kn = k0 + BK;
            #pragma unroll
            for (int r = 0; r < 2; r++){
                int gk = kn + aCol;
                pa[r] = make_float4(0.f,0.f,0.f,0.f);
                if (gk < K){
                    const float* sp = (gk < ksplit)
                        ? (A  + (long)(bRow + aRow + r*64)*lda + gk)
                        : (A2 + (long)(bRow + aRow + r*64)*lda + (gk - ksplit));
                    pa[r] = *reinterpret_cast<const float4*>(sp);
                }
            }
            int kb = kn + 2*bR;
            pbl = make_float4(0.f,0.f,0.f,0.f);
            pbh = make_float4(0.f,0.f,0.f,0.f);
            if (kb     < K) pbl = *reinterpret_cast<const float4*>(B + (long)(kb  )*ldb + bCol + bC);
            if (kb + 1 < K) pbh = *reinterpret_cast<const float4*>(B + (long)(kb+1)*ldb + bCol + bC);
        }

        // compute: one m16n8k16 step covers the whole BK=16 tile
        {
            uint32_t af[2][4];
            #pragma unroll
            for (int mi = 0; mi < 2; mi++){
                int mb = m0 + mi*16;
                af[mi][0] = As2[(tig  )*ASTR2 + mb + g    ];
                af[mi][1] = As2[(tig  )*ASTR2 + mb + g + 8];
                af[mi][2] = As2[(tig+4)*ASTR2 + mb + g    ];
                af[mi][3] = As2[(tig+4)*ASTR2 + mb + g + 8];
            }
            #pragma unroll
            for (int j = 0; j < 8; j++){
                int n = n0 + j*8 + g;
                uint32_t bf[2];
                bf[0] = Bs2[n*BSTR2 + tig    ];
                bf[1] = Bs2[n*BSTR2 + tig + 4];
                mma_f16(acc[0][j], af[0], bf);
                mma_f16(acc[1][j], af[1], bf);
            }
        }
        __syncthreads();
    }

    // epilogue: thread owns rows (m0+mi*16+g, +8), cols (n0+j*8+tig*2, +1)
    #pragma unroll
    for (int mi = 0; mi < 2; mi++){
        #pragma unroll
        for (int half = 0; half < 2; half++){
            int row = bRow + m0 + mi*16 + g + half*8;
            #pragma unroll
            for (int j = 0; j < 8; j++){
                int col = bCol + n0 + j*8 + tig*2;
                long idx = (long)row*ldc + col;
                float v0 = acc[mi][j][half*2+0] + bp[col];
                float v1 = acc[mi][j][half*2+1] + bp[col+1];
                float r0, r1;
                if (EPI == EPI_BIAS_ELU){
                    r0 = v0 > 0.f ? v0 : (expf(v0) - 1.f);
                    r1 = v1 > 0.f ? v1 : (expf(v1) - 1.f);
                } else if (EPI == EPI_BIAS_RELU){
                    r0 = fmaxf(v0, 0.f);
                    r1 = fmaxf(v1, 0.f);
                } else if (EPI == EPI_FUSION){
                    float z0 = 1.f/(1.f + expf(-v0));
                    float z1 = 1.f/(1.f + expf(-v1));
                    r0 = z0*E0[idx]   + (1.f - z0)*E1[idx];
                    r1 = z1*E0[idx+1] + (1.f - z1)*E1[idx+1];
                } else { // EPI_RESID
                    r0 = E0[idx]   + v0;
                    r1 = E0[idx+1] + v1;
                }
                *reinterpret_cast<float2*>(&C[idx]) = make_float2(r0, r1);
            }
        }
    }
}

// ---------------- host ----------------
#define SYMF(name, sym) float* name; cudaGetSymbolAddress((void**)&name, sym)
#define SYMI(name, sym) int*   name; cudaGetSymbolAddress((void**)&name, sym)

extern "C" void kernel_launch(void* const* d_in, const int* in_sizes, int n_in,
                              void* d_out, int out_size){
    const float* Hs    = (const float*)d_in[0];
    const float* Hw    = (const float*)d_in[1];
    const float* HSc   = (const float*)d_in[2];
    const int*   w2s   = (const int*)d_in[3];
    const int*   s2s   = (const int*)d_in[4];
    const int*   S2s   = (const int*)d_in[5];
    const float* Ww_src= (const float*)d_in[6];
    const float* Ww_dst= (const float*)d_in[7];
    const float* aw_src= (const float*)d_in[8];
    const float* aw_dst= (const float*)d_in[9];
    const float* bw    = (const float*)d_in[10];
    const float* Ws    = (const float*)d_in[11];
    const float* as_src= (const float*)d_in[12];
    const float* as_dst= (const float*)d_in[13];
    const float* bs    = (const float*)d_in[14];
    const float* WS_src= (const float*)d_in[15];
    const float* WS_dst= (const float*)d_in[16];
    const float* aS_src= (const float*)d_in[17];
    const float* aS_dst= (const float*)d_in[18];
    const float* bS    = (const float*)d_in[19];
    const float* Wf1   = (const float*)d_in[20];
    const float* bf1   = (const float*)d_in[21];
    const float* Wf2   = (const float*)d_in[22];
    const float* bf2   = (const float*)d_in[23];
    const float* W1    = (const float*)d_in[24];
    const float* b1    = (const float*)d_in[25];
    const float* W2    = (const float*)d_in[26];
    const float* b2    = (const float*)d_in[27];
    float* out = (float*)d_out;

    SYMF(Uw, g_Uw); SYMF(Us, g_Us); SYMF(USec, g_USec); SYMF(U1, g_U1); SYMF(U2, g_U2);
    SYMF(Gw, g_Gw); SYMF(Gs, g_Gs); SYMF(GS, g_GS); SYMF(Hh, g_Hh);
    SYMF(Pws, g_Pws); SYMF(Pwd, g_Pwd); SYMF(Pss, g_Pss); SYMF(Psd, g_Psd);
    SYMF(PSs, g_PSs); SYMF(PSd, g_PSd);
    SYMF(alws, g_alws); SYMF(alwd, g_alwd); SYMF(alss, g_alss); SYMF(alsd, g_alsd);
    SYMF(alSs, g_alSs); SYMF(alSd, g_alSd);
    SYMF(aw, g_aw); SYMF(as, g_as); SYMF(aS, g_aS);
    SYMI(mw, g_mw); SYMI(ms, g_ms); SYMI(mS, g_mS);
    SYMF(dw, g_dw); SYMF(ds, g_ds); SYMF(dS, g_dS);
    SYMI(cw, g_cw); SYMI(cs, g_cs); SYMI(cS, g_cS);
    SYMI(ow, g_ow); SYMI(os_, g_os); SYMI(oS, g_oS);
    SYMI(uw, g_uw); SYMI(us, g_us); SYMI(uS, g_uS);
    SYMI(ew, g_ew); SYMI(es, g_es); SYMI(eS, g_eS);

    const int* src_w = w2s;            const int* dst_w = w2s + EW;
    const int* src_s = s2s;            const int* dst_s = s2s + ES;
    const int* src_S = S2s;            const int* dst_S = S2s + ESEC;

    // init
    k_init_all<<<(NSENT*8+255)/256, 256>>>(mw, dw, cw, ms, ds, cs, mS, dS, cS);

    // per-head attention projection vectors
    k_P<<<300, 256>>>(Ww_src, aw_src, Pws, 300);
    k_P<<<640, 256>>>(Ww_dst, aw_dst, Pwd, 640);
    k_P<<<640, 256>>>(Ws,     as_src, Pss, 640);
    k_P<<<640, 256>>>(Ws,     as_dst, Psd, 640);
    k_P<<<512, 256>>>(WS_src, aS_src, PSs, 512);
    k_P<<<640, 256>>>(WS_dst, aS_dst, PSd, 640);

    // attention logits per node
    k_xp<<<NWORD/8, 256>>>(Hw,  Pws, alws, NWORD, 300);
    k_xp<<<NSENT/8, 256>>>(Hs,  Pwd, alwd, NSENT, 640);
    k_xp<<<NSENT/8, 256>>>(Hs,  Pss, alss, NSENT, 640);
    k_xp<<<NSENT/8, 256>>>(Hs,  Psd, alsd, NSENT, 640);
    k_xp<<<NSEC/8,  256>>>(HSc, PSs, alSs, NSEC,  512);
    k_xp<<<NSENT/8, 256>>>(Hs,  PSd, alSd, NSENT, 640);

    // CSR build
    k_count<<<EW/256, 256>>>(dst_w, cw, EW);
    k_count<<<ES/256, 256>>>(dst_s, cs, ES);
    k_count<<<ESEC/256, 256>>>(dst_S, cS, ESEC);
    k_scan<<<1, 1024>>>(cw, ow, uw);
    k_scan<<<1, 1024>>>(cs, os_, us);
    k_scan<<<1, 1024>>>(cS, oS, uS);
    k_scatter<<<EW/256, 256>>>(dst_w, uw, ew, EW);
    k_scatter<<<ES/256, 256>>>(dst_s, us, es, ES);
    k_scatter<<<ESEC/256, 256>>>(dst_S, uS, eS, ESEC);

    // edge softmax
    k_logits<<<EW/256, 256>>>(src_w, dst_w, alws, alwd, aw, mw, EW);
    k_logits<<<ES/256, 256>>>(src_s, dst_s, alss, alsd, as, ms, ES);
    k_logits<<<ESEC/256, 256>>>(src_S, dst_S, alSs, alSd, aS, mS, ESEC);
    k_exp<<<EW/256, 256>>>(dst_w, aw, mw, dw, EW);
    k_exp<<<ES/256, 256>>>(dst_s, as, ms, ds, ES);
    k_exp<<<ESEC/256, 256>>>(dst_S, aS, mS, dS, ESEC);
    k_alpha<<<EW/256, 256>>>(dst_w, aw, dw, EW);
    k_alpha<<<ES/256, 256>>>(dst_s, as, ds, ES);
    k_alpha<<<ESEC/256, 256>>>(dst_S, aS, dS, ESEC);

    // aggregate raw features per (dst, head)
    k_agg<300,2><<<NSENT, 256>>>(Hw,  src_w, ew, ow,  aw, Gw);
    k_agg<640,3><<<NSENT, 256>>>(Hs,  src_s, es, os_, as, Gs);
    k_agg<512,2><<<NSENT, 256>>>(HSc, src_S, eS, oS,  aS, GS);

    // per-head projection + bias + ELU   (batched over heads via blockIdx.z)
    dim3 gp(CDIM/BN, NSENT/BM, 8);
    gemm_k<EPI_BIAS_ELU><<<gp, 256>>>(Gw, Gw, 300, Ww_src, Uw,  bw, nullptr, nullptr,
                                      NSENT, CDIM, 300, 8*300, HC, HC, 300, 640, 640, 640);
    gemm_k<EPI_BIAS_ELU><<<gp, 256>>>(Gs, Gs, 640, Ws,     Us,  bs, nullptr, nullptr,
                                      NSENT, CDIM, 640, 8*640, HC, HC, 640, 640, 640, 640);
    gemm_k<EPI_BIAS_ELU><<<gp, 256>>>(GS, GS, 512, WS_src, USec, bS, nullptr, nullptr,
                                      NSENT, CDIM, 512, 8*512, HC, HC, 512, 640, 640, 640);

    // fusion gates: single GEMM with implicit concat (A-split), fused sigmoid-gate epilogue
    dim3 gf(HC/BN, NSENT/BM, 1);
    gemm_k<EPI_FUSION><<<gf, 256>>>(Uw, Us, HC, Wf1, U1, bf1, Uw, Us,
                                    NSENT, HC, 2*HC, HC, HC, HC, 0, 0, 0, 0);
    gemm_k<EPI_FUSION><<<gf, 256>>>(U1, USec, HC, Wf2, U2, bf2, U1, USec,
                                    NSENT, HC, 2*HC, HC, HC, HC, 0, 0, 0, 0);

    // FFN + residual
    dim3 g1(CDIM/BN, NSENT/BM, 1);
    gemm_k<EPI_BIAS_RELU><<<g1, 256>>>(U2, U2, HC, W1, Hh, b1, nullptr, nullptr,
                                       NSENT, CDIM, HC, HC, CDIM, CDIM, 0, 0, 0, 0);
    gemm_k<EPI_RESID><<<g1, 256>>>(Hh, Hh, CDIM, W2, out, b2, Hs, nullptr,
                                   NSENT, CDIM, CDIM, CDIM, CDIM, CDIM, 0, 0, 0, 0);
}